// round 3
// baseline (speedup 1.0000x reference)
#include <cuda_runtime.h>
#include <cstdint>

// ---------------- scratch (static __device__ arrays; no allocations) ----------------
__device__ float g_pool1[512*16*12*36*3];
__device__ float g_pool2[512*32*6*18*3];
__device__ float g_flat [512*64*81];     // (B, D,H,W,C)
__device__ float g_mean [512*64];

// ------- fused conv3d(3x3x3,pad1)+relu+maxpool(2,2,1), Winograd F(2,3) over h -------
// Per thread: outputs (b, oc0..oc0+NOC-1, dp, hp, w=0..2).
// h-dimension conv done in Winograd domain: 4 mults instead of 6 per (tap-row, out-pair).
// Weight transform (exact): u = (g0, (g0+g1+g2)/2, (g0-g1+g2)/2, g2), staged in smem.
// Input transform (exact adds): v = (x0-x2, x1+x2, x2-x1, x1-x3).
// Inverse: y0 = m0+m1+m2 ; y1 = m1-m2-m3.
template<int IC, int DIN, int HIN, int OCT, int NOC, int ZDIM, bool FLAT>
__global__ __launch_bounds__(432, 1)
void convpool_wino(const float* __restrict__ in,
                   const float* __restrict__ wgt,
                   const float* __restrict__ bias,
                   float* __restrict__ out)
{
    constexpr int DOUT = DIN/2, HOUT = HIN/2;
    constexpr int OCB  = NOC * ZDIM;
    constexpr int THREADS = 432;
    __shared__ float wsm[2 * OCB * 36];   // [buf][o][kd*3+kw][j]

    const int hp  = threadIdx.x;
    const int dp  = threadIdx.y;
    const int zt  = threadIdx.z;
    const int oc0 = (blockIdx.y * ZDIM + zt) * NOC;
    const int b   = blockIdx.x;
    const int t   = threadIdx.x + blockDim.x * (threadIdx.y + blockDim.y * threadIdx.z);
    const int ocb_base = blockIdx.y * OCB;

    // M[o][dd][j][w] : Winograd-domain accumulators
    float M[NOC][2][4][3];
    #pragma unroll
    for (int o = 0; o < NOC; o++)
        #pragma unroll
        for (int dd = 0; dd < 2; dd++)
            #pragma unroll
            for (int j = 0; j < 4; j++)
                #pragma unroll
                for (int w = 0; w < 3; w++) M[o][dd][j][w] = 0.f;

    const float* inb = in + (size_t)b * IC * DIN * HIN * 3;

    // cooperative weight transform staging (double buffered)
    auto stage = [&](int ic, int buf) {
        for (int i = t; i < OCB * 9; i += THREADS) {
            int o = i / 9, kk = i % 9;            // kk = kd*3 + kw
            const float* wp = wgt + ((size_t)(ocb_base + o) * IC + ic) * 27
                            + (kk / 3) * 9 + (kk % 3);
            float g0 = __ldg(wp + 0), g1 = __ldg(wp + 3), g2 = __ldg(wp + 6);
            float* ws = wsm + buf * OCB * 36 + i * 4;
            ws[0] = g0;
            ws[1] = 0.5f * (g0 + g1 + g2);
            ws[2] = 0.5f * (g0 - g1 + g2);
            ws[3] = g2;
        }
    };

    stage(0, 0);
    __syncthreads();

    #pragma unroll 1
    for (int ic = 0; ic < IC; ++ic) {
        if (ic + 1 < IC) stage(ic + 1, (ic + 1) & 1);

        const float* inc = inb + (size_t)ic * (DIN * HIN * 3);

        // load 4x4x3 patch, transform h-dim -> v[di][j][iw]
        float v[4][4][3];
        #pragma unroll
        for (int di = 0; di < 4; ++di) {
            float pv[4][3];
            int d = 2*dp - 1 + di;
            bool okd = (unsigned)d < (unsigned)DIN;
            #pragma unroll
            for (int hi = 0; hi < 4; ++hi) {
                int h = 2*hp - 1 + hi;
                bool ok = okd && ((unsigned)h < (unsigned)HIN);
                const float* rp = inc + ((size_t)d * HIN + h) * 3;
                pv[hi][0] = ok ? __ldg(rp + 0) : 0.f;
                pv[hi][1] = ok ? __ldg(rp + 1) : 0.f;
                pv[hi][2] = ok ? __ldg(rp + 2) : 0.f;
            }
            #pragma unroll
            for (int iw = 0; iw < 3; ++iw) {
                v[di][0][iw] = pv[0][iw] - pv[2][iw];
                v[di][1][iw] = pv[1][iw] + pv[2][iw];
                v[di][2][iw] = pv[2][iw] - pv[1][iw];
                v[di][3][iw] = pv[1][iw] - pv[3][iw];
            }
        }

        const float* wrow = wsm + (ic & 1) * OCB * 36 + (zt * NOC) * 36;

        #pragma unroll
        for (int o = 0; o < NOC; o++) {
            #pragma unroll
            for (int kd = 0; kd < 3; kd++)
            #pragma unroll
            for (int kw = 0; kw < 3; kw++) {
                const float* u = wrow + o * 36 + (kd * 3 + kw) * 4;
                float u0 = u[0], u1 = u[1], u2 = u[2], u3 = u[3];
                #pragma unroll
                for (int w = 0; w < 3; w++) {
                    int iw = w + kw - 1;
                    if (iw >= 0 && iw < 3) {
                        #pragma unroll
                        for (int dd = 0; dd < 2; dd++) {
                            M[o][dd][0][w] += u0 * v[dd + kd][0][iw];
                            M[o][dd][1][w] += u1 * v[dd + kd][1][iw];
                            M[o][dd][2][w] += u2 * v[dd + kd][2][iw];
                            M[o][dd][3][w] += u3 * v[dd + kd][3][iw];
                        }
                    }
                }
            }
        }
        __syncthreads();
    }

    // inverse transform + pool + bias + relu + store
    #pragma unroll
    for (int o = 0; o < NOC; o++) {
        float bv = __ldg(bias + oc0 + o);
        #pragma unroll
        for (int w = 0; w < 3; w++) {
            float y00 = M[o][0][0][w] + M[o][0][1][w] + M[o][0][2][w];
            float y01 = M[o][0][1][w] - M[o][0][2][w] - M[o][0][3][w];
            float y10 = M[o][1][0][w] + M[o][1][1][w] + M[o][1][2][w];
            float y11 = M[o][1][1][w] - M[o][1][2][w] - M[o][1][3][w];
            float vmax = fmaxf(fmaxf(y00, y01), fmaxf(y10, y11));
            vmax = fmaxf(vmax + bv, 0.f);
            if (FLAT) {
                out[(size_t)b * (DOUT*HOUT*3*OCT) + (((dp*HOUT) + hp)*3 + w) * OCT + (oc0 + o)] = vmax;
            } else {
                out[(((size_t)b * OCT + oc0 + o) * DOUT + dp) * (HOUT*3) + hp*3 + w] = vmax;
            }
        }
    }
}

// ---------------- mean over the 81 spatial positions ----------------
__global__ void mean_kernel()
{
    int b = blockIdx.x, c = threadIdx.x;
    const float* f = g_flat + (size_t)b * 5184 + c;
    float s = 0.f;
    #pragma unroll
    for (int p = 0; p < 81; p++) s += f[p * 64];
    g_mean[b * 64 + c] = s * (1.f / 81.f);
}

// ---------------- smem-tiled matvec: out[n=t][r=0..3] += W[n][k] * X[k][r] ----------------
template<int K, int KT>
__device__ __forceinline__ void matvec4(const float* __restrict__ W,
                                        const float* __restrict__ Xsh,
                                        float* __restrict__ Wsh,
                                        float acc[4], int t)
{
    constexpr int RS = KT + 4;
    constexpr int QP = KT / 4;
    for (int kt = 0; kt < K; kt += KT) {
        __syncthreads();
        #pragma unroll
        for (int i = 0; i < QP; i++) {
            int idx = t + i * 256;
            int n   = idx / QP;
            int kq  = idx % QP;
            *(float4*)(Wsh + n * RS + kq * 4) =
                *(const float4*)(W + (size_t)n * K + kt + kq * 4);
        }
        __syncthreads();
        #pragma unroll
        for (int kk = 0; kk < KT; kk += 4) {
            float4 wv = *(const float4*)(Wsh + t * RS + kk);
            float4 x0 = *(const float4*)(Xsh + (kt + kk + 0) * 4);
            float4 x1 = *(const float4*)(Xsh + (kt + kk + 1) * 4);
            float4 x2 = *(const float4*)(Xsh + (kt + kk + 2) * 4);
            float4 x3 = *(const float4*)(Xsh + (kt + kk + 3) * 4);
            acc[0] += wv.x * x0.x; acc[1] += wv.x * x0.y; acc[2] += wv.x * x0.z; acc[3] += wv.x * x0.w;
            acc[0] += wv.y * x1.x; acc[1] += wv.y * x1.y; acc[2] += wv.y * x1.z; acc[3] += wv.y * x1.w;
            acc[0] += wv.z * x2.x; acc[1] += wv.z * x2.y; acc[2] += wv.z * x2.z; acc[3] += wv.z * x2.w;
            acc[0] += wv.w * x3.x; acc[1] += wv.w * x3.y; acc[2] += wv.w * x3.z; acc[3] += wv.w * x3.w;
        }
    }
}

// ---------------- RNN decoder: 128 blocks x 4 batch rows ----------------
__global__ __launch_bounds__(256, 1)
void rnn_kernel(const float* __restrict__ whh1, const float* __restrict__ wih2,
                const float* __restrict__ whh2,
                const float* __restrict__ w_init_h,  const float* __restrict__ b_init_h,
                const float* __restrict__ w_init_h2, const float* __restrict__ b_init_h2,
                const float* __restrict__ wih1, const float* __restrict__ bih1,
                const float* __restrict__ bhh1,
                const float* __restrict__ bih2, const float* __restrict__ bhh2,
                const float* __restrict__ w_fc, const float* __restrict__ b_fc,
                float* __restrict__ preds)
{
    extern __shared__ float sm[];
    float* me   = sm;
    float* hS   = sm + 256;
    float* h2S  = sm + 1280;
    float* ihcS = sm + 2304;
    float* hnS  = sm + 3328;
    float* Wsh  = sm + 4352;

    const int t  = threadIdx.x;
    const int r0 = blockIdx.x * 4;

    { int r = t & 3, k = t >> 2;
      me[k*4 + r] = g_mean[(size_t)(r0 + r) * 64 + k]; }

    float a[4] = {0,0,0,0};
    matvec4<64,32>(w_init_h, me, Wsh, a, t);
    float c[4] = {0,0,0,0};
    matvec4<64,32>(wih1, me, Wsh, c, t);
    {
        float bh = __ldg(b_init_h + t);
        float bi = __ldg(bih1 + t) + __ldg(bhh1 + t);
        #pragma unroll
        for (int r = 0; r < 4; r++) { hS[t*4 + r] = a[r] + bh; ihcS[t*4 + r] = c[r] + bi; }
    }
    float a2[4] = {0,0,0,0};
    matvec4<256,32>(w_init_h2, hS, Wsh, a2, t);
    {
        float b2 = __ldg(b_init_h2 + t);
        #pragma unroll
        for (int r = 0; r < 4; r++) h2S[t*4 + r] = a2[r] + b2;
    }
    const float bi2 = __ldg(bih2 + t) + __ldg(bhh2 + t);
    const float bfc = __ldg(b_fc);

    for (int step = 0; step < 23; ++step) {
        float ah[4] = {0,0,0,0};
        matvec4<256,32>(whh1, hS, Wsh, ah, t);
        #pragma unroll
        for (int r = 0; r < 4; r++) hnS[t*4 + r] = tanhf(ihcS[t*4 + r] + ah[r]);
        float u[4] = {0,0,0,0};
        matvec4<256,32>(wih2, hnS, Wsh, u, t);
        float v[4] = {0,0,0,0};
        matvec4<256,32>(whh2, h2S, Wsh, v, t);
        __syncthreads();
        #pragma unroll
        for (int r = 0; r < 4; r++) {
            h2S[t*4 + r] = tanhf(u[r] + v[r] + bi2);
            hS[t*4 + r]  = hnS[t*4 + r];
        }
        __syncthreads();
        if (t < 128) {
            int r = t >> 5, lane = t & 31;
            float s = 0.f;
            #pragma unroll
            for (int k = lane; k < 256; k += 32) s += __ldg(w_fc + k) * h2S[k*4 + r];
            #pragma unroll
            for (int off = 16; off; off >>= 1) s += __shfl_down_sync(0xffffffffu, s, off);
            if (lane == 0) preds[(size_t)(r0 + r) * 23 + step] = s + bfc;
        }
    }
}

// ---------------- linear head ----------------
__global__ __launch_bounds__(256, 1)
void head_kernel(const float* __restrict__ w_lin1, const float* __restrict__ b_lin1,
                 const float* __restrict__ w_lin2, const float* __restrict__ b_lin2,
                 float* __restrict__ outc)
{
    extern __shared__ float sm[];
    float* xS  = sm;
    float* thS = sm + 20736;
    float* Wsh = sm + 21760;
    const int t  = threadIdx.x;
    const int r0 = blockIdx.x * 4;

    for (int idx = t; idx < 4 * 5184; idx += 256) {
        int r = idx / 5184, k = idx % 5184;
        xS[k*4 + r] = g_flat[(size_t)(r0 + r) * 5184 + k];
    }

    float a[4] = {0,0,0,0};
    matvec4<5184,64>(w_lin1, xS, Wsh, a, t);
    float bl = __ldg(b_lin1 + t);
    #pragma unroll
    for (int r = 0; r < 4; r++) thS[t*4 + r] = tanhf(a[r] + bl);
    __syncthreads();

    if (t < 48) {
        int n = t % 12, r = t / 12;
        float s = 0.f;
        #pragma unroll 4
        for (int k = 0; k < 256; k++) s += __ldg(w_lin2 + n*256 + k) * thS[k*4 + r];
        outc[(size_t)(r0 + r) * 12 + n] = s + __ldg(b_lin2 + n);
    }
}

// ---------------- launch ----------------
extern "C" void kernel_launch(void* const* d_in, const int* in_sizes, int n_in,
                              void* d_out, int out_size)
{
    const float* x    = (const float*)d_in[0];
    const float* w1   = (const float*)d_in[1];
    const float* b1   = (const float*)d_in[2];
    const float* w2   = (const float*)d_in[3];
    const float* b2   = (const float*)d_in[4];
    const float* w3   = (const float*)d_in[5];
    const float* b3   = (const float*)d_in[6];
    const float* wih1 = (const float*)d_in[7];
    const float* whh1 = (const float*)d_in[8];
    const float* bih1 = (const float*)d_in[9];
    const float* bhh1 = (const float*)d_in[10];
    const float* wih2 = (const float*)d_in[11];
    const float* whh2 = (const float*)d_in[12];
    const float* bih2 = (const float*)d_in[13];
    const float* bhh2 = (const float*)d_in[14];
    const float* w_init_h  = (const float*)d_in[15];
    const float* b_init_h  = (const float*)d_in[16];
    const float* w_init_h2 = (const float*)d_in[17];
    const float* b_init_h2 = (const float*)d_in[18];
    const float* w_fc  = (const float*)d_in[19];
    const float* b_fc  = (const float*)d_in[20];
    const float* w_lin1 = (const float*)d_in[21];
    const float* b_lin1 = (const float*)d_in[22];
    const float* w_lin2 = (const float*)d_in[23];
    const float* b_lin2 = (const float*)d_in[24];
    float* out = (float*)d_out;

    float *p1, *p2, *pf;
    cudaGetSymbolAddress((void**)&p1, g_pool1);
    cudaGetSymbolAddress((void**)&p2, g_pool2);
    cudaGetSymbolAddress((void**)&pf, g_flat);

    // stage 1: (512,6,24,72,3) -> (512,16,12,36,3)   NOC=2 -> 8 oc-groups
    convpool_wino<6, 24, 72, 16, 2, 1, false>
        <<<dim3(512, 8), dim3(36, 12, 1)>>>(x, w1, b1, p1);
    // stage 2: -> (512,32,6,18,3)   NOC=2, ZDIM=4 -> grid.y = 4
    convpool_wino<16, 12, 36, 32, 2, 4, false>
        <<<dim3(512, 4), dim3(18, 6, 4)>>>(p1, w2, b2, p2);
    // stage 3: -> (512, 3,9,3, 64) flat layout   NOC=2, ZDIM=16 -> grid.y = 2
    convpool_wino<32, 6, 18, 64, 2, 16, true>
        <<<dim3(512, 2), dim3(9, 3, 16)>>>(p2, w3, b3, pf);

    mean_kernel<<<512, 64>>>();

    cudaFuncSetAttribute(rnn_kernel, cudaFuncAttributeMaxDynamicSharedMemorySize, 54272);
    rnn_kernel<<<128, 256, 54272>>>(whh1, wih2, whh2,
                                    w_init_h, b_init_h, w_init_h2, b_init_h2,
                                    wih1, bih1, bhh1, bih2, bhh2,
                                    w_fc, b_fc, out);

    cudaFuncSetAttribute(head_kernel, cudaFuncAttributeMaxDynamicSharedMemorySize, 156672);
    head_kernel<<<128, 256, 156672>>>(w_lin1, b_lin1, w_lin2, b_lin2,
                                      out + 512 * 23);
}

// round 6
// speedup vs baseline: 1.0796x; 1.0796x over previous
#include <cuda_runtime.h>
#include <cstdint>

// ---------------- scratch (static __device__ arrays; no allocations) ----------------
__device__ float g_pool1[512*16*12*36*3];
__device__ float g_pool2[512*32*6*18*3];
__device__ float g_flat [512*64*81];     // (B, D,H,W,C)
__device__ float g_mean [512*64];

// ---------------- tf32 helpers ----------------
__device__ __forceinline__ unsigned f2tf(float f) {
    unsigned r; asm("cvt.rna.tf32.f32 %0, %1;" : "=r"(r) : "f"(f)); return r;
}
__device__ __forceinline__ void mma_tf32(float c[4],
    unsigned a0, unsigned a1, unsigned a2, unsigned a3,
    unsigned b0, unsigned b1)
{
    asm("mma.sync.aligned.m16n8k8.row.col.f32.tf32.tf32.f32 "
        "{%0,%1,%2,%3},{%4,%5,%6,%7},{%8,%9},{%0,%1,%2,%3};"
        : "+f"(c[0]), "+f"(c[1]), "+f"(c[2]), "+f"(c[3])
        : "r"(a0), "r"(a1), "r"(a2), "r"(a3), "r"(b0), "r"(b1));
}

// ------- fused conv3d(3x3x3,pad1)+relu+maxpool(2,2,1) as implicit GEMM on tensor cores -------
// Block = (batch b, h-tile). M = OCT, N = DIN*HT*3 positions, K = ICT*27 (grouped by ICG).
// Xs: input tile w/ zero halo [ICG][DIN+2][HT+2][5] (tf32 bits).
// Ws: weights [KGP][OCT+1] (tf32 bits), kOff[k] = ic*SIC + kd*SD + kh*5 + kw.
// B-frag addr = base(n) + kOff(k). Conv result -> smem C[OCT][NPAD] -> pool/bias/relu -> global.
template<int ICT,int ICG,int DIN,int HT,int HIN,int OCT,int NSUB,int JPW,bool FLAT>
__global__ __launch_bounds__(256,1)
void conv_tc(const float* __restrict__ in, const float* __restrict__ wgt,
             const float* __restrict__ bias, float* __restrict__ outp)
{
    constexpr int NG  = ICT/ICG;
    constexpr int KG  = ICG*27;
    constexpr int KGP = (KG+7)&~7;
    constexpr int KS  = KGP/8;
    constexpr int OCP = OCT+1;
    constexpr int SH  = 5, SD = (HT+2)*5, SIC = (DIN+2)*SD;
    constexpr int N   = DIN*HT*3;
    constexpr int MT  = OCT/16;
    constexpr int NJ  = (N + NSUB*8 - 1)/(NSUB*8);
    constexpr int NPAD = NJ*NSUB*8;
    static_assert(MT*NJ == 8*JPW, "job count mismatch");
    constexpr int DOUT = DIN/2, HTO = HT/2, HOUT = HIN/2;

    extern __shared__ unsigned smu[];
    unsigned* Ws  = smu;                         // KGP*OCP
    unsigned* Xs  = Ws + KGP*OCP;                // ICG*SIC
    int*      kOf = (int*)(Xs + ICG*SIC);        // KGP
    float*    C   = (NG > 1) ? (float*)smu       // overlay (used after final sync)
                             : (float*)(kOf + KGP);

    const int tid  = threadIdx.x;
    const int b    = blockIdx.x, ht = blockIdx.y;
    const int warp = tid >> 5, lane = tid & 31, lq = lane & 3, lg = lane >> 2;

    // ---- kOff table (group-invariant) ----
    for (int i = tid; i < KGP; i += 256) {
        int off = 0;
        if (i < KG) {
            int icl = i / 27, tap = i % 27;
            off = icl*SIC + (tap/9)*SD + ((tap/3)%3)*SH + (tap%3);
        }
        kOf[i] = off;
    }

    // ---- per-warp job geometry ----
    int baseB[JPW][NSUB];
    #pragma unroll
    for (int jj = 0; jj < JPW; jj++) {
        int job = warp + jj*8;
        int n0  = (job % NJ) * NSUB * 8;
        #pragma unroll
        for (int s = 0; s < NSUB; s++) {
            int n = n0 + s*8 + lg;
            if (n >= N) baseB[jj][s] = 0;
            else {
                int d = n / (HT*3); int r = n % (HT*3); int h = r/3, w = r%3;
                baseB[jj][s] = d*SD + h*SH + w;
            }
        }
    }

    // ---- staging lambdas ----
    auto stageW = [&](int g) {
        for (int i = tid; i < KGP*OCT; i += 256) {
            int kk = i / OCT, oc = i % OCT;
            float v = 0.f;
            if (kk < KG) {
                int icl = kk / 27, tap = kk % 27;
                v = __ldg(wgt + ((size_t)oc*ICT + g*ICG + icl)*27 + tap);
            }
            Ws[kk*OCP + oc] = f2tf(v);
        }
    };
    auto stageX = [&](int g) {
        const float* inb = in + ((size_t)b*ICT + g*ICG) * DIN * HIN * 3;
        for (int i = tid; i < ICG*SIC; i += 256) {
            int ic = i / SIC; int r = i % SIC;
            int dd = r / SD;  r %= SD;
            int hh = r / SH;  int ww = r % 5;
            int d = dd - 1, h = ht*HT + hh - 1, w = ww - 1;
            float v = 0.f;
            if ((unsigned)d < (unsigned)DIN && (unsigned)h < (unsigned)HIN && (unsigned)w < 3u)
                v = __ldg(inb + ((size_t)ic*DIN + d)*(HIN*3) + h*3 + w);
            Xs[i] = f2tf(v);
        }
    };

    if constexpr (NG == 1) {
        // ---- sequential jobs (small K): acc regs = NSUB*4 ----
        stageW(0); stageX(0);
        __syncthreads();
        #pragma unroll 1
        for (int jj = 0; jj < JPW; jj++) {
            int job = warp + jj*8;
            int m0 = (job / NJ) * 16, n0 = (job % NJ) * NSUB * 8;
            float acc[NSUB][4];
            #pragma unroll
            for (int s = 0; s < NSUB; s++)
                { acc[s][0]=0.f; acc[s][1]=0.f; acc[s][2]=0.f; acc[s][3]=0.f; }
            #pragma unroll 1
            for (int ks = 0; ks < KS; ks++) {
                int k0 = ks*8;
                unsigned a0 = Ws[(k0+lq)*OCP   + m0+lg];
                unsigned a1 = Ws[(k0+lq)*OCP   + m0+lg+8];
                unsigned a2 = Ws[(k0+4+lq)*OCP + m0+lg];
                unsigned a3 = Ws[(k0+4+lq)*OCP + m0+lg+8];
                int o0 = kOf[k0+lq], o1 = kOf[k0+4+lq];
                #pragma unroll
                for (int s = 0; s < NSUB; s++) {
                    unsigned b0 = Xs[baseB[jj][s] + o0];
                    unsigned b1 = Xs[baseB[jj][s] + o1];
                    mma_tf32(acc[s], a0,a1,a2,a3, b0,b1);
                }
            }
            #pragma unroll
            for (int s = 0; s < NSUB; s++) {
                int nn = n0 + s*8 + 2*lq;
                C[(m0+lg  )*NPAD + nn  ] = acc[s][0];
                C[(m0+lg  )*NPAD + nn+1] = acc[s][1];
                C[(m0+lg+8)*NPAD + nn  ] = acc[s][2];
                C[(m0+lg+8)*NPAD + nn+1] = acc[s][3];
            }
        }
        __syncthreads();
    } else {
        // ---- persistent accumulators across NG k-groups; C overlays smem after final sync ----
        float acc[JPW][NSUB][4];
        #pragma unroll
        for (int jj = 0; jj < JPW; jj++)
            #pragma unroll
            for (int s = 0; s < NSUB; s++)
                { acc[jj][s][0]=0.f; acc[jj][s][1]=0.f; acc[jj][s][2]=0.f; acc[jj][s][3]=0.f; }

        #pragma unroll 1
        for (int g = 0; g < NG; g++) {
            if (g) __syncthreads();
            stageW(g); stageX(g);
            __syncthreads();
            #pragma unroll 1
            for (int jj = 0; jj < JPW; jj++) {
                int job = warp + jj*8;
                int m0 = (job / NJ) * 16;
                #pragma unroll 1
                for (int ks = 0; ks < KS; ks++) {
                    int k0 = ks*8;
                    unsigned a0 = Ws[(k0+lq)*OCP   + m0+lg];
                    unsigned a1 = Ws[(k0+lq)*OCP   + m0+lg+8];
                    unsigned a2 = Ws[(k0+4+lq)*OCP + m0+lg];
                    unsigned a3 = Ws[(k0+4+lq)*OCP + m0+lg+8];
                    int o0 = kOf[k0+lq], o1 = kOf[k0+4+lq];
                    #pragma unroll
                    for (int s = 0; s < NSUB; s++) {
                        unsigned b0 = Xs[baseB[jj][s] + o0];
                        unsigned b1 = Xs[baseB[jj][s] + o1];
                        mma_tf32(acc[jj][s], a0,a1,a2,a3, b0,b1);
                    }
                }
            }
        }
        __syncthreads();   // all reads of Ws/Xs done -> safe to overlay C
        #pragma unroll
        for (int jj = 0; jj < JPW; jj++) {
            int job = warp + jj*8;
            int m0 = (job / NJ) * 16, n0 = (job % NJ) * NSUB * 8;
            #pragma unroll
            for (int s = 0; s < NSUB; s++) {
                int nn = n0 + s*8 + 2*lq;
                C[(m0+lg  )*NPAD + nn  ] = acc[jj][s][0];
                C[(m0+lg  )*NPAD + nn+1] = acc[jj][s][1];
                C[(m0+lg+8)*NPAD + nn  ] = acc[jj][s][2];
                C[(m0+lg+8)*NPAD + nn+1] = acc[jj][s][3];
            }
        }
        __syncthreads();
    }

    // ---- pool(2,2,1) + bias + relu + store ----
    constexpr int TOT = OCT * DOUT * HTO * 3;
    for (int i = tid; i < TOT; i += 256) {
        int oc = i / (DOUT*HTO*3); int r = i % (DOUT*HTO*3);
        int dp = r / (HTO*3); int r2 = r % (HTO*3); int hp = r2/3, w = r2%3;
        const float* Cr = C + (size_t)oc*NPAD;
        int n00 = ((2*dp)*HT + 2*hp)*3 + w;
        float v = fmaxf(fmaxf(Cr[n00], Cr[n00+3]),
                        fmaxf(Cr[n00+HT*3], Cr[n00+HT*3+3]));
        v = fmaxf(v + __ldg(bias + oc), 0.f);
        int hpg = ht*HTO + hp;
        if (FLAT)
            outp[(size_t)b*(DOUT*HOUT*3*OCT) + ((dp*HOUT + hpg)*3 + w)*OCT + oc] = v;
        else
            outp[((size_t)b*OCT + oc)*(DOUT*HOUT*3) + (dp*HOUT + hpg)*3 + w] = v;
    }
}

// ---------------- mean over the 81 spatial positions ----------------
__global__ void mean_kernel()
{
    int b = blockIdx.x, c = threadIdx.x;
    const float* f = g_flat + (size_t)b * 5184 + c;
    float s = 0.f;
    #pragma unroll
    for (int p = 0; p < 81; p++) s += f[p * 64];
    g_mean[b * 64 + c] = s * (1.f / 81.f);
}

// ---------------- smem-tiled matvec: out[n=t][r=0..3] += W[n][k] * X[k][r] ----------------
template<int K, int KT>
__device__ __forceinline__ void matvec4(const float* __restrict__ W,
                                        const float* __restrict__ Xsh,
                                        float* __restrict__ Wsh,
                                        float acc[4], int t)
{
    constexpr int RS = KT + 4;
    constexpr int QP = KT / 4;
    for (int kt = 0; kt < K; kt += KT) {
        __syncthreads();
        #pragma unroll
        for (int i = 0; i < QP; i++) {
            int idx = t + i * 256;
            int n   = idx / QP;
            int kq  = idx % QP;
            *(float4*)(Wsh + n * RS + kq * 4) =
                *(const float4*)(W + (size_t)n * K + kt + kq * 4);
        }
        __syncthreads();
        #pragma unroll
        for (int kk = 0; kk < KT; kk += 4) {
            float4 wv = *(const float4*)(Wsh + t * RS + kk);
            float4 x0 = *(const float4*)(Xsh + (kt + kk + 0) * 4);
            float4 x1 = *(const float4*)(Xsh + (kt + kk + 1) * 4);
            float4 x2 = *(const float4*)(Xsh + (kt + kk + 2) * 4);
            float4 x3 = *(const float4*)(Xsh + (kt + kk + 3) * 4);
            acc[0] += wv.x * x0.x; acc[1] += wv.x * x0.y; acc[2] += wv.x * x0.z; acc[3] += wv.x * x0.w;
            acc[0] += wv.y * x1.x; acc[1] += wv.y * x1.y; acc[2] += wv.y * x1.z; acc[3] += wv.y * x1.w;
            acc[0] += wv.z * x2.x; acc[1] += wv.z * x2.y; acc[2] += wv.z * x2.z; acc[3] += wv.z * x2.w;
            acc[0] += wv.w * x3.x; acc[1] += wv.w * x3.y; acc[2] += wv.w * x3.z; acc[3] += wv.w * x3.w;
        }
    }
}

// ---------------- RNN decoder: 128 blocks x 4 batch rows ----------------
__global__ __launch_bounds__(256, 1)
void rnn_kernel(const float* __restrict__ whh1, const float* __restrict__ wih2,
                const float* __restrict__ whh2,
                const float* __restrict__ w_init_h,  const float* __restrict__ b_init_h,
                const float* __restrict__ w_init_h2, const float* __restrict__ b_init_h2,
                const float* __restrict__ wih1, const float* __restrict__ bih1,
                const float* __restrict__ bhh1,
                const float* __restrict__ bih2, const float* __restrict__ bhh2,
                const float* __restrict__ w_fc, const float* __restrict__ b_fc,
                float* __restrict__ preds)
{
    extern __shared__ float sm[];
    float* me   = sm;
    float* hS   = sm + 256;
    float* h2S  = sm + 1280;
    float* ihcS = sm + 2304;
    float* hnS  = sm + 3328;
    float* Wsh  = sm + 4352;

    const int t  = threadIdx.x;
    const int r0 = blockIdx.x * 4;

    { int r = t & 3, k = t >> 2;
      me[k*4 + r] = g_mean[(size_t)(r0 + r) * 64 + k]; }

    float a[4] = {0,0,0,0};
    matvec4<64,32>(w_init_h, me, Wsh, a, t);
    float c[4] = {0,0,0,0};
    matvec4<64,32>(wih1, me, Wsh, c, t);
    {
        float bh = __ldg(b_init_h + t);
        float bi = __ldg(bih1 + t) + __ldg(bhh1 + t);
        #pragma unroll
        for (int r = 0; r < 4; r++) { hS[t*4 + r] = a[r] + bh; ihcS[t*4 + r] = c[r] + bi; }
    }
    float a2[4] = {0,0,0,0};
    matvec4<256,32>(w_init_h2, hS, Wsh, a2, t);
    {
        float b2 = __ldg(b_init_h2 + t);
        #pragma unroll
        for (int r = 0; r < 4; r++) h2S[t*4 + r] = a2[r] + b2;
    }
    const float bi2 = __ldg(bih2 + t) + __ldg(bhh2 + t);
    const float bfc = __ldg(b_fc);

    for (int step = 0; step < 23; ++step) {
        float ah[4] = {0,0,0,0};
        matvec4<256,32>(whh1, hS, Wsh, ah, t);
        #pragma unroll
        for (int r = 0; r < 4; r++) hnS[t*4 + r] = tanhf(ihcS[t*4 + r] + ah[r]);
        float u[4] = {0,0,0,0};
        matvec4<256,32>(wih2, hnS, Wsh, u, t);
        float v[4] = {0,0,0,0};
        matvec4<256,32>(whh2, h2S, Wsh, v, t);
        __syncthreads();
        #pragma unroll
        for (int r = 0; r < 4; r++) {
            h2S[t*4 + r] = tanhf(u[r] + v[r] + bi2);
            hS[t*4 + r]  = hnS[t*4 + r];
        }
        __syncthreads();
        if (t < 128) {
            int r = t >> 5, lane = t & 31;
            float s = 0.f;
            #pragma unroll
            for (int k = lane; k < 256; k += 32) s += __ldg(w_fc + k) * h2S[k*4 + r];
            #pragma unroll
            for (int off = 16; off; off >>= 1) s += __shfl_down_sync(0xffffffffu, s, off);
            if (lane == 0) preds[(size_t)(r0 + r) * 23 + step] = s + bfc;
        }
    }
}

// ---------------- linear head ----------------
__global__ __launch_bounds__(256, 1)
void head_kernel(const float* __restrict__ w_lin1, const float* __restrict__ b_lin1,
                 const float* __restrict__ w_lin2, const float* __restrict__ b_lin2,
                 float* __restrict__ outc)
{
    extern __shared__ float sm[];
    float* xS  = sm;
    float* thS = sm + 20736;
    float* Wsh = sm + 21760;
    const int t  = threadIdx.x;
    const int r0 = blockIdx.x * 4;

    for (int idx = t; idx < 4 * 5184; idx += 256) {
        int r = idx / 5184, k = idx % 5184;
        xS[k*4 + r] = g_flat[(size_t)(r0 + r) * 5184 + k];
    }

    float a[4] = {0,0,0,0};
    matvec4<5184,64>(w_lin1, xS, Wsh, a, t);
    float bl = __ldg(b_lin1 + t);
    #pragma unroll
    for (int r = 0; r < 4; r++) thS[t*4 + r] = tanhf(a[r] + bl);
    __syncthreads();

    if (t < 48) {
        int n = t % 12, r = t / 12;
        float s = 0.f;
        #pragma unroll 4
        for (int k = 0; k < 256; k++) s += __ldg(w_lin2 + n*256 + k) * thS[k*4 + r];
        outc[(size_t)(r0 + r) * 12 + n] = s + __ldg(b_lin2 + n);
    }
}

// ---------------- launch ----------------
extern "C" void kernel_launch(void* const* d_in, const int* in_sizes, int n_in,
                              void* d_out, int out_size)
{
    const float* x    = (const float*)d_in[0];
    const float* w1   = (const float*)d_in[1];
    const float* b1   = (const float*)d_in[2];
    const float* w2   = (const float*)d_in[3];
    const float* b2   = (const float*)d_in[4];
    const float* w3   = (const float*)d_in[5];
    const float* b3   = (const float*)d_in[6];
    const float* wih1 = (const float*)d_in[7];
    const float* whh1 = (const float*)d_in[8];
    const float* bih1 = (const float*)d_in[9];
    const float* bhh1 = (const float*)d_in[10];
    const float* wih2 = (const float*)d_in[11];
    const float* whh2 = (const float*)d_in[12];
    const float* bih2 = (const float*)d_in[13];
    const float* bhh2 = (const float*)d_in[14];
    const float* w_init_h  = (const float*)d_in[15];
    const float* b_init_h  = (const float*)d_in[16];
    const float* w_init_h2 = (const float*)d_in[17];
    const float* b_init_h2 = (const float*)d_in[18];
    const float* w_fc  = (const float*)d_in[19];
    const float* b_fc  = (const float*)d_in[20];
    const float* w_lin1 = (const float*)d_in[21];
    const float* b_lin1 = (const float*)d_in[22];
    const float* w_lin2 = (const float*)d_in[23];
    const float* b_lin2 = (const float*)d_in[24];
    float* out = (float*)d_out;

    float *p1, *p2, *pf;
    cudaGetSymbolAddress((void**)&p1, g_pool1);
    cudaGetSymbolAddress((void**)&p2, g_pool2);
    cudaGetSymbolAddress((void**)&pf, g_flat);

    // stage 1: ICT=6,ICG=6, D24,HT24,H72, OC16, NSUB=9, JPW=3   smem=203808B
    auto k1 = conv_tc<6,6,24,24,72,16,9,3,false>;
    cudaFuncSetAttribute(k1, cudaFuncAttributeMaxDynamicSharedMemorySize, 203808);
    k1<<<dim3(512,3), 256, 203808>>>(x, w1, b1, p1);

    // stage 2: ICT=16,ICG=16, D12,HT12,H36, OC32, NSUB=7, JPW=2  smem=178816B
    auto k2 = conv_tc<16,16,12,12,36,32,7,2,false>;
    cudaFuncSetAttribute(k2, cudaFuncAttributeMaxDynamicSharedMemorySize, 178816);
    k2<<<dim3(512,3), 256, 178816>>>(p1, w2, b2, p2);

    // stage 3: ICT=32,ICG=16 (2 groups), D6,HT18,H18, OC64, NSUB=8, JPW=3  smem=165248B
    auto k3 = conv_tc<32,16,6,18,18,64,8,3,true>;
    cudaFuncSetAttribute(k3, cudaFuncAttributeMaxDynamicSharedMemorySize, 165248);
    k3<<<dim3(512,1), 256, 165248>>>(p2, w3, b3, pf);

    mean_kernel<<<512, 64>>>();

    cudaFuncSetAttribute(rnn_kernel, cudaFuncAttributeMaxDynamicSharedMemorySize, 54272);
    rnn_kernel<<<128, 256, 54272>>>(whh1, wih2, whh2,
                                    w_init_h, b_init_h, w_init_h2, b_init_h2,
                                    wih1, bih1, bhh1, bih2, bhh2,
                                    w_fc, b_fc, out);

    cudaFuncSetAttribute(head_kernel, cudaFuncAttributeMaxDynamicSharedMemorySize, 156672);
    head_kernel<<<128, 256, 156672>>>(w_lin1, b_lin1, w_lin2, b_lin2,
                                      out + 512 * 23);
}